// round 13
// baseline (speedup 1.0000x reference)
#include <cuda_runtime.h>
#include <math_constants.h>

#define NN     8192      // nodes
#define FIN    256
#define NH     128
#define NE     524288    // edges (= 2^19)
#define TOPK   32
#define SEGCAP 1024      // max segment size supported (actual max ~110)

// ---- XLA ReduceWindowRewriter blocked-scan geometry, base_length = 16 ----
// levels: 2^19 -> 2^15 -> 2^11 -> 2^7 -> 2^3 (<=16: direct serial)
#define SB     16
#define N0     (NE / SB)       // 32768 level-0 rows / totals T0
#define N1     (N0 / SB)       // 2048  totals T1
#define N2     (N1 / SB)       // 128   totals T2
#define N3     (N2 / SB)       // 8     totals T3 (direct serial scan)

// ---------------- device scratch (no allocations allowed) ----------------
__device__ float g_a[NN];
__device__ float g_b[NN];
__device__ float g_z[NE];      // per-edge z (input order)
__device__ int   g_cnt[NN];
__device__ int   g_cur[NN];
__device__ int   g_off[NN + 1];
__device__ float g_zb[NE];     // z bucketed by segment (unsorted within segment)
__device__ int   g_cb[NE];     // col bucketed by segment
__device__ float g_zs[NE];     // z bucketed + sorted desc within segment
__device__ float g_cs[NE];     // I0 then final cumsum (reduce_window semantics)
__device__ float g_t0[N0];     // level-0 row totals
__device__ float g_i1[N0];     // inner scans over T0 -> finalized SC_T0
__device__ float g_t1[N1];
__device__ float g_i2[N1];     // inner scans over T1 -> finalized SC_T1
__device__ float g_t2[N2];
__device__ float g_i3[N2];     // inner scans over T2 -> finalized SC_T2
__device__ float g_t3[N3];

// ---------------- zero counters ----------------
__global__ void zero_cnt_kernel() {
    int i = blockIdx.x * blockDim.x + threadIdx.x;
    if (i < NN) { g_cnt[i] = 0; g_cur[i] = 0; }
}

// ---------------- GEMM: h = relu(x @ W1 + b1), M=8192,N=128,K=256 --------
// (bitwise-matches reference output0 — serial ascending-k FMA accumulation,
//  then +bias, then relu. Do not change accumulation order.)
__global__ __launch_bounds__(128) void gemm_relu_kernel(
    const float* __restrict__ x, const float* __restrict__ W1,
    const float* __restrict__ b1, float* __restrict__ h)
{
    __shared__ float As[32][64];    // [k][m]
    __shared__ float Bs[32][128];   // [k][n]
    const int tid = threadIdx.x;
    const int block_row = blockIdx.x * 64;
    const int tn = tid & 15;
    const int tm = tid >> 4;

    float acc[8][8];
#pragma unroll
    for (int i = 0; i < 8; i++)
#pragma unroll
        for (int j = 0; j < 8; j++) acc[i][j] = 0.f;

    for (int k0 = 0; k0 < FIN; k0 += 32) {
#pragma unroll
        for (int q = 0; q < 4; q++) {
            int p = tid + q * 128;
            int row = p >> 3;
            int k4  = (p & 7) * 4;
            float4 v = *(const float4*)&x[(size_t)(block_row + row) * FIN + k0 + k4];
            As[k4 + 0][row] = v.x; As[k4 + 1][row] = v.y;
            As[k4 + 2][row] = v.z; As[k4 + 3][row] = v.w;
        }
#pragma unroll
        for (int q = 0; q < 8; q++) {
            int p = tid + q * 128;
            int kk = p >> 5;
            int c4 = (p & 31) * 4;
            *(float4*)&Bs[kk][c4] = *(const float4*)&W1[(size_t)(k0 + kk) * NH + c4];
        }
        __syncthreads();
#pragma unroll
        for (int kk = 0; kk < 32; kk++) {
            float af[8], bf[8];
#pragma unroll
            for (int i = 0; i < 8; i++) af[i] = As[kk][tm * 8 + i];
#pragma unroll
            for (int j = 0; j < 8; j++) bf[j] = Bs[kk][tn * 8 + j];
#pragma unroll
            for (int i = 0; i < 8; i++)
#pragma unroll
                for (int j = 0; j < 8; j++) acc[i][j] += af[i] * bf[j];
        }
        __syncthreads();
    }

    float bb[8];
#pragma unroll
    for (int j = 0; j < 8; j++) bb[j] = b1[tn * 8 + j];

#pragma unroll
    for (int i = 0; i < 8; i++) {
        int r = block_row + tm * 8 + i;
#pragma unroll
        for (int j0 = 0; j0 < 8; j0 += 4) {
            float4 v;
            v.x = fmaxf(acc[i][j0 + 0] + bb[j0 + 0], 0.f);
            v.y = fmaxf(acc[i][j0 + 1] + bb[j0 + 1], 0.f);
            v.z = fmaxf(acc[i][j0 + 2] + bb[j0 + 2], 0.f);
            v.w = fmaxf(acc[i][j0 + 3] + bb[j0 + 3], 0.f);
            *(float4*)&h[(size_t)r * NH + tn * 8 + j0] = v;
        }
    }
}

// ---------------- per-node dots (z low bits cancel downstream) -----------
__global__ void node_dots_kernel(const float* __restrict__ h,
                                 const float* __restrict__ We)
{
    int n = blockIdx.x * blockDim.x + threadIdx.x;
    if (n >= NN) return;
    const float* hr = h + (size_t)n * NH;
    float sa = 0.f, sb = 0.f;
#pragma unroll 16
    for (int k = 0; k < NH; k++) {
        float hv = hr[k];
        sa = __fmaf_rn(hv, We[k],      sa);
        sb = __fmaf_rn(hv, We[NH + k], sb);
    }
    g_a[n] = sa;
    g_b[n] = sb;
}

// ---------------- per-edge z + per-row histogram ----------------
// z = fl(fl(a[row] + b[col]) + be)
__global__ void edge_z_hist_kernel(const int* __restrict__ ei,
                                   const float* __restrict__ be)
{
    int e = blockIdx.x * blockDim.x + threadIdx.x;
    if (e >= NE) return;
    int r = ei[e];
    int c = ei[NE + e];
    g_z[e] = __fadd_rn(__fadd_rn(g_a[r], g_b[c]), be[0]);
    atomicAdd(&g_cnt[r], 1);
}

// ---------------- exclusive scan of counts (single block) ----------------
__global__ __launch_bounds__(1024) void scan_off_kernel()
{
    __shared__ int sums[1024];
    int tid = threadIdx.x;
    int base = tid * 8;
    int local[8];
    int s = 0;
#pragma unroll
    for (int i = 0; i < 8; i++) { local[i] = s; s += g_cnt[base + i]; }
    sums[tid] = s;
    __syncthreads();
    for (int d = 1; d < 1024; d <<= 1) {
        int v = (tid >= d) ? sums[tid - d] : 0;
        __syncthreads();
        sums[tid] += v;
        __syncthreads();
    }
    int excl = (tid == 0) ? 0 : sums[tid - 1];
#pragma unroll
    for (int i = 0; i < 8; i++) g_off[base + i] = excl + local[i];
    if (tid == 1023) g_off[NN] = sums[1023];
}

// ---------------- bucket edges by segment ----------------
__global__ void bucket_kernel(const int* __restrict__ ei)
{
    int e = blockIdx.x * blockDim.x + threadIdx.x;
    if (e >= NE) return;
    int r = ei[e];
    int c = ei[NE + e];
    int p = atomicAdd(&g_cur[r], 1);
    int d = g_off[r] + p;
    g_zb[d] = g_z[e];
    g_cb[d] = c;
}

// ---------------- per-segment bitonic sort (desc) -> g_zs ----------------
__global__ __launch_bounds__(128) void sort_seg_kernel()
{
    const int seg = blockIdx.x;
    const int beg = g_off[seg];
    int cnt = g_off[seg + 1] - beg;
    if (cnt <= 0) return;
    if (cnt > SEGCAP) cnt = SEGCAP;

    __shared__ float zs[SEGCAP];
    const int tid = threadIdx.x;

    int n2 = 1;
    while (n2 < cnt) n2 <<= 1;

    for (int i = tid; i < n2; i += 128)
        zs[i] = (i < cnt) ? g_zb[beg + i] : -CUDART_INF_F;
    __syncthreads();

    for (int k = 2; k <= n2; k <<= 1) {
        for (int j = k >> 1; j > 0; j >>= 1) {
            for (int i = tid; i < n2; i += 128) {
                int ixj = i ^ j;
                if (ixj > i) {
                    bool desc = ((i & k) == 0);
                    float x0 = zs[i], x1 = zs[ixj];
                    bool sw = desc ? (x0 < x1) : (x0 > x1);
                    if (sw) { zs[i] = x1; zs[ixj] = x0; }
                }
            }
            __syncthreads();
        }
    }

    for (int i = tid; i < cnt; i += 128)
        g_zs[beg + i] = zs[i];
}

// ============ cumsum: XLA ReduceWindowRewriter, base_length = 16 ==========
// Inner scans (length 16) are reduce_windows evaluated elementwise =
// serial left folds from 0 (fl(0+x)=x exact). Totals recursively scanned
// with the same scheme. Carries applied one level at a time, each as a
// single rounded add fl(carry + inner).

__global__ void scan16_fold0_kernel()
{
    int r = blockIdx.x * blockDim.x + threadIdx.x;
    if (r >= N0) return;
    const int base = r * SB;
    float run = 0.f;
#pragma unroll
    for (int j = 0; j < SB; j++) {
        run = __fadd_rn(run, g_zs[base + j]);
        g_cs[base + j] = run;           // I0
    }
    g_t0[r] = run;                      // T0
}

__global__ __launch_bounds__(1024) void scan16_mid_kernel()
{
    __shared__ float s4[N3];            // serial scan of T3
    const int tid = threadIdx.x;

    // L1: inner scans over T0 -> I1, totals T1   (N1 = 2048 rows)
    for (int r = tid; r < N1; r += 1024) {
        const int base = r * SB;
        float run = 0.f;
#pragma unroll
        for (int j = 0; j < SB; j++) {
            run = __fadd_rn(run, g_t0[base + j]);
            g_i1[base + j] = run;
        }
        g_t1[r] = run;
    }
    __syncthreads();

    // L2: inner scans over T1 -> I2, totals T2   (N2 = 128 rows)
    if (tid < N2) {
        const int base = tid * SB;
        float run = 0.f;
#pragma unroll
        for (int j = 0; j < SB; j++) {
            run = __fadd_rn(run, g_t1[base + j]);
            g_i2[base + j] = run;
        }
        g_t2[tid] = run;
    }
    __syncthreads();

    // L3: inner scans over T2 -> I3, totals T3   (N3 = 8 rows)
    if (tid < N3) {
        const int base = tid * SB;
        float run = 0.f;
#pragma unroll
        for (int j = 0; j < SB; j++) {
            run = __fadd_rn(run, g_t2[base + j]);
            g_i3[base + j] = run;
        }
        g_t3[tid] = run;
    }
    __syncthreads();

    // L4: direct serial scan of T3 (8 <= base, left as reduce_window)
    if (tid == 0) {
        float run = 0.f;
        for (int q = 0; q < N3; q++) {
            run = __fadd_rn(run, g_t3[q]);
            s4[q] = run;
        }
    }
    __syncthreads();

    // combine: SC_T2[m] = fl(E(s4)[m/16] + I3[m])     (in place over g_i3)
    if (tid < N2) {
        int q = tid / SB;
        float e = (q == 0) ? 0.f : s4[q - 1];
        g_i3[tid] = __fadd_rn(e, g_i3[tid]);
    }
    __syncthreads();

    // combine: SC_T1[m] = fl(E(SC_T2)[m/16] + I2[m])  (in place over g_i2)
    for (int m = tid; m < N1; m += 1024) {
        int p = m / SB;
        float e = (p == 0) ? 0.f : g_i3[p - 1];
        g_i2[m] = __fadd_rn(e, g_i2[m]);
    }
    __syncthreads();

    // combine: SC_T0[m] = fl(E(SC_T1)[m/16] + I1[m])  (in place over g_i1)
    for (int m = tid; m < N0; m += 1024) {
        int r = m / SB;
        float e = (r == 0) ? 0.f : g_i2[r - 1];
        g_i1[m] = __fadd_rn(e, g_i1[m]);
    }
}

__global__ void scan16_final_kernel()
{
    int i = blockIdx.x * blockDim.x + threadIdx.x;
    if (i >= NE) return;
    int m = i / SB;
    float e = (m == 0) ? 0.f : g_i1[m - 1];   // E(SC_T0)
    g_cs[i] = __fadd_rn(e, g_cs[i]);
}

// ---------------- finalize: kmax/tau exactly as reference, scatter ------
__global__ __launch_bounds__(128) void finalize_kernel(float* __restrict__ adj)
{
    const int seg = blockIdx.x;
    const int beg = g_off[seg];
    int cnt = g_off[seg + 1] - beg;
    if (cnt <= 0) return;
    if (cnt > SEGCAP) cnt = SEGCAP;

    const int tid = threadIdx.x;
    __shared__ int s_kmax;
    if (tid == 0) s_kmax = 1;
    __syncthreads();

    // prefix[start] = fl(cs[start] - zs[start])
    const float pstart = __fsub_rn(g_cs[beg], g_zs[beg]);

    int lm = 0;
    for (int j = tid; j < cnt; j += 128) {
        float zsj   = g_zs[beg + j];
        float segcs = __fsub_rn(g_cs[beg + j], pstart);
        float lhs   = __fadd_rn(1.0f, __fmul_rn((float)(j + 1), zsj));
        if (lhs > segcs && (j + 1) > lm) lm = j + 1;
    }
    if (lm > 0) atomicMax(&s_kmax, lm);
    __syncthreads();

    const int kmax = s_kmax;
    const float seg_cs_at_k = __fsub_rn(g_cs[beg + kmax - 1], pstart);
    const float tau = __fdiv_rn(__fsub_rn(seg_cs_at_k, 1.0f), (float)kmax);
    const float th  = (kmax >= TOPK) ? __fsub_rn(g_zs[beg + TOPK - 1], tau) : 0.0f;

    for (int i = tid; i < cnt; i += 128) {
        float sc = __fsub_rn(g_zb[beg + i], tau);
        if (sc > 0.0f && sc >= th)
            adj[(size_t)seg * NN + g_cb[beg + i]] = sc;
    }
}

// ---------------- launcher ----------------
extern "C" void kernel_launch(void* const* d_in, const int* in_sizes, int n_in,
                              void* d_out, int out_size)
{
    const float* x  = (const float*)d_in[0];
    const int*   ei = (const int*)  d_in[1];
    const float* W1 = (const float*)d_in[2];
    const float* b1 = (const float*)d_in[3];
    const float* We = (const float*)d_in[4];
    const float* be = (const float*)d_in[5];

    float* out = (float*)d_out;
    float* h   = out;                       // 8192*128
    float* adj = out + (size_t)NN * NH;     // 8192*8192

    (void)in_sizes; (void)n_in; (void)out_size;

    zero_cnt_kernel<<<(NN + 255) / 256, 256>>>();
    cudaMemsetAsync(adj, 0, (size_t)NN * NN * sizeof(float), 0);
    gemm_relu_kernel<<<NN / 64, 128>>>(x, W1, b1, h);
    node_dots_kernel<<<NN / 256, 256>>>(h, We);
    edge_z_hist_kernel<<<(NE + 511) / 512, 512>>>(ei, be);
    scan_off_kernel<<<1, 1024>>>();
    bucket_kernel<<<(NE + 511) / 512, 512>>>(ei);
    sort_seg_kernel<<<NN, 128>>>();

    // cumsum with XLA ReduceWindowRewriter(base=16) fp32 semantics
    scan16_fold0_kernel<<<N0 / 256, 256>>>();
    scan16_mid_kernel<<<1, 1024>>>();
    scan16_final_kernel<<<NE / 256, 256>>>();

    finalize_kernel<<<NN, 128>>>(adj);
}

// round 14
// speedup vs baseline: 1.1078x; 1.1078x over previous
#include <cuda_runtime.h>
#include <math_constants.h>

#define NN     8192      // nodes
#define FIN    256
#define NH     128
#define NE     524288    // edges (= 2^19)
#define TOPK   32
#define SEGCAP 1024      // max segment size supported (actual max ~110)

// ---- XLA ReduceWindowRewriter blocked-scan geometry, base_length = 16 ----
#define SB     16
#define N0     (NE / SB)       // 32768
#define N1     (N0 / SB)       // 2048
#define N2     (N1 / SB)       // 128
#define N3     (N2 / SB)       // 8

// ---------------- device scratch (no allocations allowed) ----------------
__device__ float g_a[NN];
__device__ float g_b[NN];
__device__ int   g_cnt[NN];     // zero-initialized; re-zeroed by sort_seg each call
__device__ int   g_cur[NN];
__device__ int   g_off[NN + 1];
__device__ float g_zb[NE];     // z bucketed by segment (unsorted within segment)
__device__ int   g_cb[NE];     // col bucketed by segment
__device__ float g_zs[NE];     // z bucketed + sorted desc within segment
__device__ float g_cs[NE];     // I0 then final cumsum (reduce_window semantics)
__device__ float g_t0[N0];
__device__ float g_i1[N0];
__device__ float g_t1[N1];
__device__ float g_i2[N1];
__device__ float g_t2[N2];
__device__ float g_i3[N2];
__device__ float g_t3[N3];

// ---------------- GEMM + fused node dots ---------------------------------
// h = relu(x @ W1 + b1); a[n] = h[n]@We[:128]; b[n] = h[n]@We[128:]
// BM=64, BN=128(=NH), BK=32, 256 threads, 4x8 per thread.
// Each block owns complete h rows -> dots computed in epilogue via
// 16-lane shfl reduction over the column threads.
__global__ __launch_bounds__(256) void gemm_relu_kernel(
    const float* __restrict__ x, const float* __restrict__ W1,
    const float* __restrict__ b1, const float* __restrict__ We,
    float* __restrict__ h)
{
    __shared__ float As[32][64];    // [k][m]
    __shared__ float Bs[32][128];   // [k][n]
    __shared__ float sWe[2 * NH];
    const int tid = threadIdx.x;
    const int block_row = blockIdx.x * 64;
    const int tn = tid & 15;        // 16 threads x 8 cols = 128
    const int tm = tid >> 4;        // 16 groups x 4 rows = 64

    if (tid < 64) ((float4*)sWe)[tid] = ((const float4*)We)[tid];

    float acc[4][8];
#pragma unroll
    for (int i = 0; i < 4; i++)
#pragma unroll
        for (int j = 0; j < 8; j++) acc[i][j] = 0.f;

    for (int k0 = 0; k0 < FIN; k0 += 32) {
#pragma unroll
        for (int q = 0; q < 2; q++) {
            int p = tid + q * 256;           // 0..511
            int row = p >> 3;
            int k4  = (p & 7) * 4;
            float4 v = *(const float4*)&x[(size_t)(block_row + row) * FIN + k0 + k4];
            As[k4 + 0][row] = v.x; As[k4 + 1][row] = v.y;
            As[k4 + 2][row] = v.z; As[k4 + 3][row] = v.w;
        }
#pragma unroll
        for (int q = 0; q < 4; q++) {
            int p = tid + q * 256;           // 0..1023
            int kk = p >> 5;
            int c4 = (p & 31) * 4;
            *(float4*)&Bs[kk][c4] = *(const float4*)&W1[(size_t)(k0 + kk) * NH + c4];
        }
        __syncthreads();
#pragma unroll
        for (int kk = 0; kk < 32; kk++) {
            float af[4], bf[8];
#pragma unroll
            for (int i = 0; i < 4; i++) af[i] = As[kk][tm * 4 + i];
#pragma unroll
            for (int j = 0; j < 8; j++) bf[j] = Bs[kk][tn * 8 + j];
#pragma unroll
            for (int i = 0; i < 4; i++)
#pragma unroll
                for (int j = 0; j < 8; j++) acc[i][j] += af[i] * bf[j];
        }
        __syncthreads();
    }

    float bb[8];
#pragma unroll
    for (int j = 0; j < 8; j++) bb[j] = b1[tn * 8 + j];

#pragma unroll
    for (int i = 0; i < 4; i++) {
        int r = block_row + tm * 4 + i;
        float hv[8];
#pragma unroll
        for (int j = 0; j < 8; j++) hv[j] = fmaxf(acc[i][j] + bb[j], 0.f);

        float4 v0 = make_float4(hv[0], hv[1], hv[2], hv[3]);
        float4 v1 = make_float4(hv[4], hv[5], hv[6], hv[7]);
        *(float4*)&h[(size_t)r * NH + tn * 8]     = v0;
        *(float4*)&h[(size_t)r * NH + tn * 8 + 4] = v1;

        // fused dots (order-free: z low bits cancel downstream)
        float pa = 0.f, pb = 0.f;
#pragma unroll
        for (int j = 0; j < 8; j++) {
            pa = __fmaf_rn(hv[j], sWe[tn * 8 + j],      pa);
            pb = __fmaf_rn(hv[j], sWe[NH + tn * 8 + j], pb);
        }
#pragma unroll
        for (int o = 8; o > 0; o >>= 1) {
            pa += __shfl_xor_sync(0xffffffffu, pa, o);
            pb += __shfl_xor_sync(0xffffffffu, pb, o);
        }
        if (tn == 0) { g_a[r] = pa; g_b[r] = pb; }
    }
}

// ---------------- per-row histogram (4 edges/thread) ----------------------
__global__ void hist_kernel(const int* __restrict__ ei)
{
    int t = blockIdx.x * blockDim.x + threadIdx.x;
    if (t >= NE / 4) return;
    int4 r4 = ((const int4*)ei)[t];
    atomicAdd(&g_cnt[r4.x], 1);
    atomicAdd(&g_cnt[r4.y], 1);
    atomicAdd(&g_cnt[r4.z], 1);
    atomicAdd(&g_cnt[r4.w], 1);
}

// ---------------- exclusive scan of counts (single block) ----------------
__global__ __launch_bounds__(1024) void scan_off_kernel()
{
    __shared__ int sums[1024];
    int tid = threadIdx.x;
    int base = tid * 8;
    int local[8];
    int s = 0;
#pragma unroll
    for (int i = 0; i < 8; i++) { local[i] = s; s += g_cnt[base + i]; }
    sums[tid] = s;
    __syncthreads();
    for (int d = 1; d < 1024; d <<= 1) {
        int v = (tid >= d) ? sums[tid - d] : 0;
        __syncthreads();
        sums[tid] += v;
        __syncthreads();
    }
    int excl = (tid == 0) ? 0 : sums[tid - 1];
#pragma unroll
    for (int i = 0; i < 8; i++) g_off[base + i] = excl + local[i];
    if (tid == 1023) g_off[NN] = sums[1023];
}

// ---------------- bucket edges by segment (z computed here) ---------------
// z = fl(fl(a[row] + b[col]) + be)
__global__ void bucket_kernel(const int* __restrict__ ei,
                              const float* __restrict__ be)
{
    int e = blockIdx.x * blockDim.x + threadIdx.x;
    if (e >= NE) return;
    int r = ei[e];
    int c = ei[NE + e];
    float z = __fadd_rn(__fadd_rn(g_a[r], g_b[c]), be[0]);
    int p = atomicAdd(&g_cur[r], 1);
    int d = g_off[r] + p;
    g_zb[d] = z;
    g_cb[d] = c;
}

// ---------------- per-segment bitonic sort (desc) -> g_zs -----------------
// Also re-zeroes g_cnt/g_cur for the NEXT call (deterministic: globals are
// zero-init on first call, restored here for every replay).
__global__ __launch_bounds__(128) void sort_seg_kernel()
{
    const int seg = blockIdx.x;
    const int tid = threadIdx.x;
    if (tid == 0) { g_cnt[seg] = 0; g_cur[seg] = 0; }

    const int beg = g_off[seg];
    int cnt = g_off[seg + 1] - beg;
    if (cnt <= 0) return;
    if (cnt > SEGCAP) cnt = SEGCAP;

    __shared__ float zs[SEGCAP];

    int n2 = 1;
    while (n2 < cnt) n2 <<= 1;

    for (int i = tid; i < n2; i += 128)
        zs[i] = (i < cnt) ? g_zb[beg + i] : -CUDART_INF_F;
    __syncthreads();

    for (int k = 2; k <= n2; k <<= 1) {
        for (int j = k >> 1; j > 0; j >>= 1) {
            for (int i = tid; i < n2; i += 128) {
                int ixj = i ^ j;
                if (ixj > i) {
                    bool desc = ((i & k) == 0);
                    float x0 = zs[i], x1 = zs[ixj];
                    bool sw = desc ? (x0 < x1) : (x0 > x1);
                    if (sw) { zs[i] = x1; zs[ixj] = x0; }
                }
            }
            __syncthreads();
        }
    }

    for (int i = tid; i < cnt; i += 128)
        g_zs[beg + i] = zs[i];
}

// ============ cumsum: XLA ReduceWindowRewriter, base_length = 16 ==========
__global__ void scan16_fold0_kernel()
{
    int r = blockIdx.x * blockDim.x + threadIdx.x;
    if (r >= N0) return;
    const float4* src = (const float4*)(g_zs + r * SB);
    float4 v[4];
#pragma unroll
    for (int q = 0; q < 4; q++) v[q] = src[q];
    float buf[16] = { v[0].x, v[0].y, v[0].z, v[0].w,
                      v[1].x, v[1].y, v[1].z, v[1].w,
                      v[2].x, v[2].y, v[2].z, v[2].w,
                      v[3].x, v[3].y, v[3].z, v[3].w };
    float out[16];
    float run = 0.f;
#pragma unroll
    for (int j = 0; j < SB; j++) {
        run = __fadd_rn(run, buf[j]);
        out[j] = run;
    }
    float4* dst = (float4*)(g_cs + r * SB);
#pragma unroll
    for (int q = 0; q < 4; q++)
        dst[q] = make_float4(out[q*4], out[q*4+1], out[q*4+2], out[q*4+3]);
    g_t0[r] = run;
}

__global__ __launch_bounds__(1024) void scan16_mid_kernel()
{
    __shared__ float s4[N3];
    const int tid = threadIdx.x;

    // L1: inner scans over T0 -> I1, totals T1   (N1 = 2048 rows)
    for (int r = tid; r < N1; r += 1024) {
        const int base = r * SB;
        float run = 0.f;
#pragma unroll
        for (int j = 0; j < SB; j++) {
            run = __fadd_rn(run, g_t0[base + j]);
            g_i1[base + j] = run;
        }
        g_t1[r] = run;
    }
    __syncthreads();

    // L2: inner scans over T1 -> I2, totals T2   (N2 = 128 rows)
    if (tid < N2) {
        const int base = tid * SB;
        float run = 0.f;
#pragma unroll
        for (int j = 0; j < SB; j++) {
            run = __fadd_rn(run, g_t1[base + j]);
            g_i2[base + j] = run;
        }
        g_t2[tid] = run;
    }
    __syncthreads();

    // L3: inner scans over T2 -> I3, totals T3   (N3 = 8 rows)
    if (tid < N3) {
        const int base = tid * SB;
        float run = 0.f;
#pragma unroll
        for (int j = 0; j < SB; j++) {
            run = __fadd_rn(run, g_t2[base + j]);
            g_i3[base + j] = run;
        }
        g_t3[tid] = run;
    }
    __syncthreads();

    // L4: direct serial scan of T3
    if (tid == 0) {
        float run = 0.f;
        for (int q = 0; q < N3; q++) {
            run = __fadd_rn(run, g_t3[q]);
            s4[q] = run;
        }
    }
    __syncthreads();

    // combine: SC_T2 = fl(E(s4) + I3)   (in place over g_i3)
    if (tid < N2) {
        int q = tid / SB;
        float e = (q == 0) ? 0.f : s4[q - 1];
        g_i3[tid] = __fadd_rn(e, g_i3[tid]);
    }
    __syncthreads();

    // combine: SC_T1 = fl(E(SC_T2) + I2)   (in place over g_i2)
    for (int m = tid; m < N1; m += 1024) {
        int p = m / SB;
        float e = (p == 0) ? 0.f : g_i3[p - 1];
        g_i2[m] = __fadd_rn(e, g_i2[m]);
    }
    __syncthreads();

    // combine: SC_T0 = fl(E(SC_T1) + I1)   (in place over g_i1)
    for (int m = tid; m < N0; m += 1024) {
        int r = m / SB;
        float e = (r == 0) ? 0.f : g_i2[r - 1];
        g_i1[m] = __fadd_rn(e, g_i1[m]);
    }
}

__global__ void scan16_final_kernel()
{
    int t = blockIdx.x * blockDim.x + threadIdx.x;   // one float4 per thread
    if (t >= NE / 4) return;
    int m = t / 4;                                    // 16-block index (4 float4 per block)
    float e = (m == 0) ? 0.f : g_i1[m - 1];
    float4 v = ((const float4*)g_cs)[t];
    v.x = __fadd_rn(e, v.x);
    v.y = __fadd_rn(e, v.y);
    v.z = __fadd_rn(e, v.z);
    v.w = __fadd_rn(e, v.w);
    ((float4*)g_cs)[t] = v;
}

// ---------------- finalize: tau/thresh + FULL row write (replaces memset) -
__global__ __launch_bounds__(256) void finalize_kernel(float* __restrict__ adj)
{
    __shared__ float row[NN];      // 32 KB
    __shared__ int s_kmax;
    const int seg = blockIdx.x;
    const int tid = threadIdx.x;
    const int beg = g_off[seg];
    int cnt = g_off[seg + 1] - beg;
    if (cnt > SEGCAP) cnt = SEGCAP;

    float4 z4 = make_float4(0.f, 0.f, 0.f, 0.f);
#pragma unroll
    for (int q = 0; q < NN / 4 / 256; q++)           // 8 iters
        ((float4*)row)[tid + q * 256] = z4;
    if (tid == 0) s_kmax = 1;
    __syncthreads();

    if (cnt > 0) {
        // prefix[start] = fl(cs[start] - zs[start])
        const float pstart = __fsub_rn(g_cs[beg], g_zs[beg]);

        int lm = 0;
        for (int j = tid; j < cnt; j += 256) {
            float zsj   = g_zs[beg + j];
            float segcs = __fsub_rn(g_cs[beg + j], pstart);
            float lhs   = __fadd_rn(1.0f, __fmul_rn((float)(j + 1), zsj));
            if (lhs > segcs && (j + 1) > lm) lm = j + 1;
        }
        if (lm > 0) atomicMax(&s_kmax, lm);
        __syncthreads();

        const int kmax = s_kmax;
        const float seg_cs_at_k = __fsub_rn(g_cs[beg + kmax - 1], pstart);
        const float tau = __fdiv_rn(__fsub_rn(seg_cs_at_k, 1.0f), (float)kmax);
        const float th  = (kmax >= TOPK) ? __fsub_rn(g_zs[beg + TOPK - 1], tau) : 0.0f;

        for (int i = tid; i < cnt; i += 256) {
            float sc = __fsub_rn(g_zb[beg + i], tau);
            if (sc > 0.0f && sc >= th)
                row[g_cb[beg + i]] = sc;        // duplicate (r,c) => identical z => same value
        }
    }
    __syncthreads();

    float4* dst = (float4*)(adj + (size_t)seg * NN);
#pragma unroll
    for (int q = 0; q < NN / 4 / 256; q++)           // 8 float4 stores/thread
        dst[tid + q * 256] = ((float4*)row)[tid + q * 256];
}

// ---------------- launcher ----------------
extern "C" void kernel_launch(void* const* d_in, const int* in_sizes, int n_in,
                              void* d_out, int out_size)
{
    const float* x  = (const float*)d_in[0];
    const int*   ei = (const int*)  d_in[1];
    const float* W1 = (const float*)d_in[2];
    const float* b1 = (const float*)d_in[3];
    const float* We = (const float*)d_in[4];
    const float* be = (const float*)d_in[5];

    float* out = (float*)d_out;
    float* h   = out;                       // 8192*128
    float* adj = out + (size_t)NN * NH;     // 8192*8192 (fully written by finalize)

    (void)in_sizes; (void)n_in; (void)out_size;

    gemm_relu_kernel<<<NN / 64, 256>>>(x, W1, b1, We, h);
    hist_kernel<<<(NE / 4 + 255) / 256, 256>>>(ei);
    scan_off_kernel<<<1, 1024>>>();
    bucket_kernel<<<(NE + 511) / 512, 512>>>(ei, be);
    sort_seg_kernel<<<NN, 128>>>();

    // cumsum with XLA ReduceWindowRewriter(base=16) fp32 semantics
    scan16_fold0_kernel<<<N0 / 256, 256>>>();
    scan16_mid_kernel<<<1, 1024>>>();
    scan16_final_kernel<<<NE / 4 / 256, 256>>>();

    finalize_kernel<<<NN, 256>>>(adj);
}